// round 3
// baseline (speedup 1.0000x reference)
#include <cuda_runtime.h>
#include <cuda_fp16.h>
#include <math.h>

// ---------------- problem constants ----------------
#define NB 2
#define NV 3
#define NC 32
#define ND 48
#define NH 128
#define NW 160
#define NHW (NH*NW)          // 20480

// ---------------- fused kernel tiling ----------------
#define TH 16
#define TW 32
#define HHs (TH+2)           // 18
#define HWs (TW+2)           // 34
#define HALO (HHs*HWs)       // 612
#define CH 16                // depth outputs per block
#define NCHUNK (ND/CH)       // 3

// smem layout sizes (bytes)
#define SZ_VAR  (8*HALO*16)      // 78336  float4 [cg][p]
#define SZ_REF  (8*HALO*8)       // 39168  uint2(4xhalf) [cg][p]
#define SZ_OFF  (2*HALO*16)      // 19584  int4 [view][p]
#define SZ_WB   (2*HALO*16)      // 19584  float4 [view][p]
#define SZ_WC   (9*8*12*4)       // 3456   conv weights
#define SMEM_BYTES (SZ_VAR+SZ_REF+SZ_OFF+SZ_WB+SZ_WC)   // 160128 -> 1 block/SM

// ---------------- device scratch ----------------
__device__ __align__(16) float g_refT[(size_t)NB*8*NHW*4];       // [b][cg][px] float4
__device__ __align__(16) uint2 g_srcH[(size_t)2*NB*8*NHW];       // [v-1][b][cg][px] 4xhalf
__device__ float g_cost[(size_t)NB*ND*NHW];                      // (B,D,H,W)
__device__ float g_rot[NB][2][9];
__device__ float g_trans[NB][2][3];
__device__ float g_wc[9*8*12];                                   // [(kh*3+kw)][cg][kd*4+c4]
__device__ float g_bias;

// ---------------- prep: proj @ inv(ref_proj), weight relayout ----------------
__global__ void prep_kernel(const float* __restrict__ proj,
                            const float* __restrict__ rw,
                            const float* __restrict__ rb) {
    int tid = threadIdx.x;
    // relayout reg_w (1,C,3,3,3): rw[c*27 + kd*9 + kh*3 + kw]
    for (int i = tid; i < 27*NC; i += blockDim.x) {
        int c = i / 27, k = i - c*27;
        int kd = k / 9, kh = (k - kd*9) / 3, kw = k % 3;
        int cg = c >> 2, c4 = c & 3;
        g_wc[((kh*3 + kw)*8 + cg)*12 + kd*4 + c4] = rw[i];
    }
    if (tid == 0) g_bias = rb[0];
    if (tid < NB) {
        int b = tid;
        const float* refp = proj + ((size_t)b*NV + 0)*16;
        double a[4][8];
        for (int r = 0; r < 4; r++)
            for (int c2 = 0; c2 < 4; c2++) {
                a[r][c2] = (double)refp[r*4+c2];
                a[r][4+c2] = (r == c2) ? 1.0 : 0.0;
            }
        for (int col = 0; col < 4; col++) {
            int p = col; double best = fabs(a[col][col]);
            for (int r = col+1; r < 4; r++) {
                double v = fabs(a[r][col]);
                if (v > best) { best = v; p = r; }
            }
            if (p != col)
                for (int c2 = 0; c2 < 8; c2++) {
                    double t = a[col][c2]; a[col][c2] = a[p][c2]; a[p][c2] = t;
                }
            double pi = 1.0 / a[col][col];
            for (int c2 = 0; c2 < 8; c2++) a[col][c2] *= pi;
            for (int r = 0; r < 4; r++) if (r != col) {
                double f = a[r][col];
                for (int c2 = 0; c2 < 8; c2++) a[r][c2] -= f*a[col][c2];
            }
        }
        for (int v = 1; v < NV; v++) {
            const float* S = proj + ((size_t)b*NV + v)*16;
            for (int r = 0; r < 3; r++) {
                double pr[4];
                for (int c2 = 0; c2 < 4; c2++) {
                    double s = 0.0;
                    for (int k = 0; k < 4; k++) s += (double)S[r*4+k]*a[k][4+c2];
                    pr[c2] = s;
                }
                g_rot[b][v-1][r*3+0] = (float)pr[0];
                g_rot[b][v-1][r*3+1] = (float)pr[1];
                g_rot[b][v-1][r*3+2] = (float)pr[2];
                g_trans[b][v-1][r]   = (float)pr[3];
            }
        }
    }
}

// ---------------- stage: (V,B,C,H,W) -> ref fp32 cg-blocked + src fp16 cg-blocked ----
__global__ void stage_kernel(const float* __restrict__ feat) {
    __shared__ float t[32][33];
    int vb = blockIdx.y;               // v*NB + b
    int hw0 = blockIdx.x * 32;
    const float* src = feat + (size_t)vb*NC*NHW;
    #pragma unroll
    for (int cc = threadIdx.y; cc < 32; cc += 8)
        t[cc][threadIdx.x] = src[(size_t)cc*NHW + hw0 + threadIdx.x];
    __syncthreads();
    int v = vb / NB, b = vb - v*NB;
    int cg = threadIdx.y;              // 0..7
    int tx = threadIdx.x;
    float4 val = make_float4(t[4*cg+0][tx], t[4*cg+1][tx], t[4*cg+2][tx], t[4*cg+3][tx]);
    size_t idx = ((size_t)b*8 + cg)*NHW + hw0 + tx;
    if (v == 0) {
        ((float4*)g_refT)[idx] = val;
    } else {
        __half2 h01 = __floats2half2_rn(val.x, val.y);
        __half2 h23 = __floats2half2_rn(val.z, val.w);
        uint2 u;
        u.x = *reinterpret_cast<unsigned*>(&h01);
        u.y = *reinterpret_cast<unsigned*>(&h23);
        g_srcH[(size_t)(v-1)*NB*8*NHW + idx] = u;
    }
}

__device__ __forceinline__ float4 unpackh4(uint2 u) {
    __half2 h01 = *reinterpret_cast<__half2*>(&u.x);
    __half2 h23 = *reinterpret_cast<__half2*>(&u.y);
    float2 f01 = __half22float2(h01);
    float2 f23 = __half22float2(h23);
    return make_float4(f01.x, f01.y, f23.x, f23.y);
}

// ---------------- fused warp + variance + conv3d -> cost (d-outer ring) -------------
__global__ __launch_bounds__(256, 1)
void fused_cost_kernel(const float* __restrict__ dvals) {
    extern __shared__ unsigned char smem_raw[];
    float4* sVar = (float4*)smem_raw;                     // [cg][p]
    uint2*  sRef = (uint2*)(smem_raw + SZ_VAR);           // [cg][p]
    int4*   sOff = (int4*)(smem_raw + SZ_VAR + SZ_REF);   // [view][p]
    float4* sWb  = (float4*)(smem_raw + SZ_VAR + SZ_REF + SZ_OFF);  // [view][p]
    float*  sWc  = (float*)(smem_raw + SZ_VAR + SZ_REF + SZ_OFF + SZ_WB);

    const int tid = threadIdx.x;
    const int w0 = blockIdx.x * TW;
    const int h0 = blockIdx.y * TH;
    const int bz = blockIdx.z;
    const int b = bz / NCHUNK;
    const int d0 = (bz - b*NCHUNK) * CH;

    for (int i = tid; i < 9*8*12; i += 256) sWc[i] = g_wc[i];

    float R[2][9], T[2][3];
    #pragma unroll
    for (int v = 0; v < 2; v++) {
        #pragma unroll
        for (int k = 0; k < 9; k++) R[v][k] = g_rot[b][v][k];
        #pragma unroll
        for (int k = 0; k < 3; k++) T[v][k] = g_trans[b][v][k];
    }

    // hoist depth-invariant ref feature for halo tile into smem (fp16)
    for (int i = tid; i < 8*HALO; i += 256) {
        int cg = i / HALO, p = i - cg*HALO;
        int r = p / HWs, c = p - r*HWs;
        int h = h0 + r - 1, w = w0 + c - 1;
        float4 rv = make_float4(0.f, 0.f, 0.f, 0.f);
        if ((unsigned)h < (unsigned)NH && (unsigned)w < (unsigned)NW)
            rv = __ldg((const float4*)g_refT + (((size_t)b*8 + cg)*NHW + h*NW + w));
        __half2 h01 = __floats2half2_rn(rv.x, rv.y);
        __half2 h23 = __floats2half2_rn(rv.z, rv.w);
        uint2 u;
        u.x = *reinterpret_cast<unsigned*>(&h01);
        u.y = *reinterpret_cast<unsigned*>(&h23);
        sRef[i] = u;
    }

    const int lhh = tid >> 4;     // 0..15 output row in tile
    const int wt  = tid & 15;     // 0..15, outputs w = 2wt, 2wt+1
    const int lw2 = wt*2;

    float aP0=0.f, aP1=0.f, aC0=0.f, aC1=0.f, aN0=0.f, aN1=0.f;

    const uint2* src1 = g_srcH + (size_t)(0*NB + b)*8*NHW;
    const uint2* src2 = g_srcH + (size_t)(1*NB + b)*8*NHW;

    __syncthreads();

    const float bias = g_bias;

    for (int s = d0 - 1; s <= d0 + CH; s++) {
        const bool active = (s >= 0 && s < ND);
        if (active) {
            const float dep = __ldg(&dvals[b*ND + s]);
            // ---- per-slice bilinear offsets + weights (shared by all cg) ----
            for (int p = tid; p < HALO; p += 256) {
                int r = p / HWs, c = p - r*HWs;
                int h = h0 + r - 1, w = w0 + c - 1;
                bool valid = ((unsigned)h < (unsigned)NH && (unsigned)w < (unsigned)NW);
                float fx = (float)w, fy = (float)h;
                #pragma unroll
                for (int v = 0; v < 2; v++) {
                    float rx = R[v][0]*fx + R[v][1]*fy + R[v][2];
                    float ry = R[v][3]*fx + R[v][4]*fy + R[v][5];
                    float rz = R[v][6]*fx + R[v][7]*fy + R[v][8];
                    float px = rx*dep + T[v][0];
                    float py = ry*dep + T[v][1];
                    float pz = rz*dep + T[v][2];
                    if (fabsf(pz) < 1e-6f) pz = 1e-6f;
                    px = px / pz;
                    py = py / pz;
                    float x0f = floorf(px), y0f = floorf(py);
                    float wx1 = px - x0f, wy1 = py - y0f;
                    float wx0 = 1.f - wx1, wy0 = 1.f - wy1;
                    float x1f = x0f + 1.f, y1f = y0f + 1.f;
                    float vx0 = (x0f >= 0.f && x0f <= (float)(NW-1)) ? 1.f : 0.f;
                    float vx1 = (x1f >= 0.f && x1f <= (float)(NW-1)) ? 1.f : 0.f;
                    float vy0 = (y0f >= 0.f && y0f <= (float)(NH-1)) ? 1.f : 0.f;
                    float vy1 = (y1f >= 0.f && y1f <= (float)(NH-1)) ? 1.f : 0.f;
                    float vv = valid ? 1.f : 0.f;
                    int ix0 = (int)fminf(fmaxf(x0f, 0.f), (float)(NW-1));
                    int ix1 = (int)fminf(fmaxf(x1f, 0.f), (float)(NW-1));
                    int iy0 = (int)fminf(fmaxf(y0f, 0.f), (float)(NH-1));
                    int iy1 = (int)fminf(fmaxf(y1f, 0.f), (float)(NH-1));
                    float4 wq = make_float4(wx0*wy0*vx0*vy0*vv, wx1*wy0*vx1*vy0*vv,
                                            wx0*wy1*vx0*vy1*vv, wx1*wy1*vx1*vy1*vv);
                    int4 oq = make_int4(iy0*NW+ix0, iy0*NW+ix1, iy1*NW+ix0, iy1*NW+ix1);
                    sOff[v*HALO + p] = oq;
                    sWb[v*HALO + p]  = wq;
                }
            }
            __syncthreads();
            // ---- variance slice for all 8 cg ----
            for (int i = tid; i < 8*HALO; i += 256) {
                int cg = i / HALO, p = i - cg*HALO;
                float4 rv = unpackh4(sRef[i]);
                float s0 = rv.x, s1 = rv.y, s2 = rv.z, s3 = rv.w;
                float q0 = rv.x*rv.x, q1 = rv.y*rv.y, q2 = rv.z*rv.z, q3 = rv.w*rv.w;
                const size_t cgo = (size_t)cg*NHW;
                {
                    int4 o = sOff[p]; float4 wq = sWb[p];
                    const uint2* bp = src1 + cgo;
                    float4 f00 = unpackh4(__ldg(bp + o.x));
                    float4 f01 = unpackh4(__ldg(bp + o.y));
                    float4 f10 = unpackh4(__ldg(bp + o.z));
                    float4 f11 = unpackh4(__ldg(bp + o.w));
                    float a0 = f00.x*wq.x + f01.x*wq.y + f10.x*wq.z + f11.x*wq.w;
                    float a1 = f00.y*wq.x + f01.y*wq.y + f10.y*wq.z + f11.y*wq.w;
                    float a2 = f00.z*wq.x + f01.z*wq.y + f10.z*wq.z + f11.z*wq.w;
                    float a3 = f00.w*wq.x + f01.w*wq.y + f10.w*wq.z + f11.w*wq.w;
                    s0 += a0; q0 += a0*a0; s1 += a1; q1 += a1*a1;
                    s2 += a2; q2 += a2*a2; s3 += a3; q3 += a3*a3;
                }
                {
                    int4 o = sOff[HALO + p]; float4 wq = sWb[HALO + p];
                    const uint2* bp = src2 + cgo;
                    float4 f00 = unpackh4(__ldg(bp + o.x));
                    float4 f01 = unpackh4(__ldg(bp + o.y));
                    float4 f10 = unpackh4(__ldg(bp + o.z));
                    float4 f11 = unpackh4(__ldg(bp + o.w));
                    float a0 = f00.x*wq.x + f01.x*wq.y + f10.x*wq.z + f11.x*wq.w;
                    float a1 = f00.y*wq.x + f01.y*wq.y + f10.y*wq.z + f11.y*wq.w;
                    float a2 = f00.z*wq.x + f01.z*wq.y + f10.z*wq.z + f11.z*wq.w;
                    float a3 = f00.w*wq.x + f01.w*wq.y + f10.w*wq.z + f11.w*wq.w;
                    s0 += a0; q0 += a0*a0; s1 += a1; q1 += a1*a1;
                    s2 += a2; q2 += a2*a2; s3 += a3; q3 += a3*a3;
                }
                const float inv3 = (1.f/3.f);
                float m0 = s0*inv3, m1 = s1*inv3, m2 = s2*inv3, m3 = s3*inv3;
                sVar[i] = make_float4(q0*inv3 - m0*m0, q1*inv3 - m1*m1,
                                      q2*inv3 - m2*m2, q3*inv3 - m3*m3);
            }
        }
        __syncthreads();
        if (active) {
            // ---- contribution-style 3x3x3 conv for this slice ----
            #pragma unroll 1
            for (int cg = 0; cg < 8; cg++) {
                #pragma unroll
                for (int kh = 0; kh < 3; kh++) {
                    const float4* row = sVar + cg*HALO + (lhh + kh)*HWs + lw2;
                    float4 v0 = row[0], v1 = row[1], v2 = row[2], v3 = row[3];
                    #pragma unroll
                    for (int kw = 0; kw < 3; kw++) {
                        const float* wk = sWc + ((kh*3 + kw)*8 + cg)*12;
                        float4 wN = *(const float4*)(wk);      // kd=0 -> o=s+1
                        float4 wC = *(const float4*)(wk + 4);  // kd=1 -> o=s
                        float4 wP = *(const float4*)(wk + 8);  // kd=2 -> o=s-1
                        float4 ta = (kw == 0) ? v0 : ((kw == 1) ? v1 : v2);
                        float4 tb = (kw == 0) ? v1 : ((kw == 1) ? v2 : v3);
                        aN0 += ta.x*wN.x + ta.y*wN.y + ta.z*wN.z + ta.w*wN.w;
                        aC0 += ta.x*wC.x + ta.y*wC.y + ta.z*wC.z + ta.w*wC.w;
                        aP0 += ta.x*wP.x + ta.y*wP.y + ta.z*wP.z + ta.w*wP.w;
                        aN1 += tb.x*wN.x + tb.y*wN.y + tb.z*wN.z + tb.w*wN.w;
                        aC1 += tb.x*wC.x + tb.y*wC.y + tb.z*wC.z + tb.w*wC.w;
                        aP1 += tb.x*wP.x + tb.y*wP.y + tb.z*wP.z + tb.w*wP.w;
                    }
                }
            }
        }
        __syncthreads();
        // emit output o = s-1 (completed)
        int o = s - 1;
        if (o >= d0 && o < d0 + CH) {
            float2* cp = (float2*)(g_cost + (((size_t)b*ND + o)*NH + (h0 + lhh))*NW + w0 + lw2);
            *cp = make_float2(aP0 + bias, aP1 + bias);
        }
        aP0 = aC0; aP1 = aC1;
        aC0 = aN0; aC1 = aN1;
        aN0 = 0.f; aN1 = 0.f;
    }
}

// ---------------- softmax over depth + expected depth + confidence ----------------
__global__ __launch_bounds__(256)
void softmax_kernel(const float* __restrict__ dvals, float* __restrict__ out) {
    int gid = blockIdx.x*blockDim.x + threadIdx.x;
    if (gid >= NB*NHW) return;
    int b = gid / NHW;
    int hw = gid - b*NHW;
    const float* cp = g_cost + (size_t)b*ND*NHW + hw;
    float c[ND];
    float mx = -3.4e38f;
    #pragma unroll
    for (int d = 0; d < ND; d++) {
        c[d] = cp[(size_t)d*NHW];
        mx = fmaxf(mx, c[d]);
    }
    float sum = 0.f;
    #pragma unroll
    for (int d = 0; d < ND; d++) {
        c[d] = __expf(c[d] - mx);
        sum += c[d];
    }
    float inv = 1.f/sum;
    float depth = 0.f, fidx = 0.f;
    #pragma unroll
    for (int d = 0; d < ND; d++) {
        depth += c[d]*__ldg(&dvals[b*ND + d]);
        fidx  += c[d]*(float)d;
    }
    depth *= inv;
    fidx  *= inv;
    int di = (int)fidx;
    di = min(max(di, 0), ND-1);
    float conf = 0.f;
    #pragma unroll
    for (int d = 0; d < ND; d++) {
        if (d >= di-1 && d <= di+2) conf += c[d];
    }
    conf *= inv;
    out[gid] = depth;
    out[NB*NHW + gid] = conf;
}

// ---------------- launch ----------------
extern "C" void kernel_launch(void* const* d_in, const int* in_sizes, int n_in,
                              void* d_out, int out_size) {
    const float* features = (const float*)d_in[0];   // (V,B,C,H,W)
    const float* proj     = (const float*)d_in[1];   // (B,V,4,4)
    const float* dvals    = (const float*)d_in[2];   // (B,D)
    int iw = 3;
    while (iw < n_in && in_sizes[iw] != 27*NC) iw++;
    const float* rw = (const float*)d_in[iw];
    const float* rb = (const float*)d_in[iw+1];

    cudaFuncSetAttribute(fused_cost_kernel,
                         cudaFuncAttributeMaxDynamicSharedMemorySize, SMEM_BYTES);

    prep_kernel<<<1, 256>>>(proj, rw, rb);
    stage_kernel<<<dim3(NHW/32, NV*NB), dim3(32, 8)>>>(features);
    fused_cost_kernel<<<dim3(NW/TW, NH/TH, NB*NCHUNK), 256, SMEM_BYTES>>>(dvals);
    softmax_kernel<<<(NB*NHW + 255)/256, 256>>>(dvals, (float*)d_out);
}

// round 4
// speedup vs baseline: 1.2470x; 1.2470x over previous
#include <cuda_runtime.h>
#include <cuda_bf16.h>
#include <math.h>

// ---------------- problem constants ----------------
#define NB 2
#define NV 3
#define NC 32
#define ND 48
#define NH 128
#define NW 160
#define NHW (NH*NW)          // 20480

// ---------------- fused kernel tiling ----------------
#define TD 6
#define TH 8
#define TW 32
#define HD (TD+2)            // 8
#define HHs (TH+2)           // 10
#define HWs (TW+2)           // 34
#define PLANE (HHs*HWs)      // 340
#define NHALO (HD*PLANE)     // 2720
#define SMEM_BYTES (NHALO*16*2 + 27*NC*4)   // sVar + sPos + weights = 90496 -> 2 blocks/SM

// ---------------- device scratch (static; no runtime alloc) ----------------
// Feature staging layout: (V, B, CG=8, H, W, 4ch) fp32 -> pixel stride 16B.
__device__ __align__(128) float g_featT[(size_t)NV*NB*NHW*NC];
__device__ float g_cost[(size_t)NB*ND*NHW];                   // (B,D,H,W)
__device__ float g_rot[NB][2][9];
__device__ float g_trans[NB][2][3];
__device__ float g_w[27*NC];                                  // [tap27][c]
__device__ float g_bias;

#define CG_PLANE ((size_t)NHW)              // float4 elements per cg-plane
#define VB_STRIDE ((size_t)8*NHW)           // float4 elements per (v,b)

// ---------------- prep: proj @ inv(ref_proj), weight relayout ----------------
__global__ void prep_kernel(const float* __restrict__ proj,
                            const float* __restrict__ rw,
                            const float* __restrict__ rb) {
    int tid = threadIdx.x;
    for (int i = tid; i < 27*NC; i += blockDim.x) {
        int cc = i / 27, k = i - cc*27;
        g_w[k*NC + cc] = rw[i];
    }
    if (tid == 0) g_bias = rb[0];
    if (tid < NB) {
        int b = tid;
        const float* refp = proj + ((size_t)b*NV + 0)*16;
        double a[4][8];
        for (int r = 0; r < 4; r++)
            for (int c2 = 0; c2 < 4; c2++) {
                a[r][c2] = (double)refp[r*4+c2];
                a[r][4+c2] = (r == c2) ? 1.0 : 0.0;
            }
        for (int col = 0; col < 4; col++) {
            int p = col; double best = fabs(a[col][col]);
            for (int r = col+1; r < 4; r++) {
                double v = fabs(a[r][col]);
                if (v > best) { best = v; p = r; }
            }
            if (p != col)
                for (int c2 = 0; c2 < 8; c2++) {
                    double t = a[col][c2]; a[col][c2] = a[p][c2]; a[p][c2] = t;
                }
            double pi = 1.0 / a[col][col];
            for (int c2 = 0; c2 < 8; c2++) a[col][c2] *= pi;
            for (int r = 0; r < 4; r++) if (r != col) {
                double f = a[r][col];
                for (int c2 = 0; c2 < 8; c2++) a[r][c2] -= f*a[col][c2];
            }
        }
        for (int v = 1; v < NV; v++) {
            const float* S = proj + ((size_t)b*NV + v)*16;
            for (int r = 0; r < 3; r++) {
                double pr[4];
                for (int c2 = 0; c2 < 4; c2++) {
                    double s = 0.0;
                    for (int k = 0; k < 4; k++) s += (double)S[r*4+k]*a[k][4+c2];
                    pr[c2] = s;
                }
                g_rot[b][v-1][r*3+0] = (float)pr[0];
                g_rot[b][v-1][r*3+1] = (float)pr[1];
                g_rot[b][v-1][r*3+2] = (float)pr[2];
                g_trans[b][v-1][r]   = (float)pr[3];
            }
        }
    }
}

// ---------------- transpose (V,B,C,H,W) -> (V,B,cg,H,W,4) ----------------
__global__ void transpose_kernel(const float* __restrict__ feat) {
    __shared__ float t[32][33];
    int vb = blockIdx.y;
    int hw0 = blockIdx.x * 32;
    const float* src = feat + (size_t)vb*NC*NHW;
    #pragma unroll
    for (int cc = threadIdx.y; cc < 32; cc += 8)
        t[cc][threadIdx.x] = src[(size_t)cc*NHW + hw0 + threadIdx.x];
    __syncthreads();
    float* dst = g_featT + (size_t)vb*VB_STRIDE*4;
    int c = threadIdx.x;
    int cg = c >> 2, c4 = c & 3;
    #pragma unroll
    for (int r = threadIdx.y; r < 32; r += 8)
        dst[((size_t)cg*CG_PLANE + hw0 + r)*4 + c4] = t[c][r];
}

// ---------------- bilinear sample of 4 channels ----------------
__device__ __forceinline__ void bilin4(const float4* __restrict__ base, float px, float py,
                                       float& s0, float& s1, float& s2, float& s3,
                                       float& q0, float& q1, float& q2, float& q3) {
    float x0f = floorf(px), y0f = floorf(py);
    float wx1 = px - x0f, wy1 = py - y0f;
    float wx0 = 1.f - wx1, wy0 = 1.f - wy1;
    float x1f = x0f + 1.f, y1f = y0f + 1.f;
    float vx0 = (x0f >= 0.f && x0f <= (float)(NW-1)) ? 1.f : 0.f;
    float vx1 = (x1f >= 0.f && x1f <= (float)(NW-1)) ? 1.f : 0.f;
    float vy0 = (y0f >= 0.f && y0f <= (float)(NH-1)) ? 1.f : 0.f;
    float vy1 = (y1f >= 0.f && y1f <= (float)(NH-1)) ? 1.f : 0.f;
    int ix0 = (int)fminf(fmaxf(x0f, 0.f), (float)(NW-1));
    int ix1 = (int)fminf(fmaxf(x1f, 0.f), (float)(NW-1));
    int iy0 = (int)fminf(fmaxf(y0f, 0.f), (float)(NH-1));
    int iy1 = (int)fminf(fmaxf(y1f, 0.f), (float)(NH-1));
    float w00 = wx0*wy0*vx0*vy0;
    float w01 = wx1*wy0*vx1*vy0;
    float w10 = wx0*wy1*vx0*vy1;
    float w11 = wx1*wy1*vx1*vy1;
    const float4 f00 = __ldg(base + (iy0*NW + ix0));
    const float4 f01 = __ldg(base + (iy0*NW + ix1));
    const float4 f10 = __ldg(base + (iy1*NW + ix0));
    const float4 f11 = __ldg(base + (iy1*NW + ix1));
    float a0 = f00.x*w00 + f01.x*w01 + f10.x*w10 + f11.x*w11;
    float a1 = f00.y*w00 + f01.y*w01 + f10.y*w10 + f11.y*w11;
    float a2 = f00.z*w00 + f01.z*w01 + f10.z*w10 + f11.z*w11;
    float a3 = f00.w*w00 + f01.w*w01 + f10.w*w10 + f11.w*w11;
    s0 += a0; q0 += a0*a0;
    s1 += a1; q1 += a1*a1;
    s2 += a2; q2 += a2*a2;
    s3 += a3; q3 += a3*a3;
}

// ---------------- fused warp + variance + conv3d -> cost ----------------
__global__ __launch_bounds__(256, 2)
void fused_cost_kernel(const float* __restrict__ dvals) {
    extern __shared__ unsigned char smem_raw[];
    float4* sVar = (float4*)smem_raw;            // [dd][p] for current cg
    float4* sPos = sVar + NHALO;                 // [dd][p] warped coords (both views)
    float*  sW   = (float*)(sPos + NHALO);

    const int tid = threadIdx.x;
    const int bz = blockIdx.z;
    const int b  = bz / (ND/TD);
    const int d0 = (bz - b*(ND/TD)) * TD;
    const int h0 = blockIdx.y * TH;
    const int w0 = blockIdx.x * TW;

    for (int i = tid; i < 27*NC; i += 256) sW[i] = g_w[i];

    float R[2][9], T[2][3];
    #pragma unroll
    for (int v = 0; v < 2; v++) {
        #pragma unroll
        for (int k = 0; k < 9; k++) R[v][k] = g_rot[b][v][k];
        #pragma unroll
        for (int k = 0; k < 3; k++) T[v][k] = g_trans[b][v][k];
    }

    // Phase 0: per-(dd,p) warped coords; rotation hoisted per p, depth inner
    for (int p = tid; p < PLANE; p += 256) {
        int hh = p / HWs;
        int ww = p - hh*HWs;
        int h = h0 + hh - 1, w = w0 + ww - 1;
        if ((unsigned)h >= (unsigned)NH || (unsigned)w >= (unsigned)NW) continue;
        float fx = (float)w, fy = (float)h;
        float rx[2], ry[2], rz[2];
        #pragma unroll
        for (int v = 0; v < 2; v++) {
            rx[v] = R[v][0]*fx + R[v][1]*fy + R[v][2];
            ry[v] = R[v][3]*fx + R[v][4]*fy + R[v][5];
            rz[v] = R[v][6]*fx + R[v][7]*fy + R[v][8];
        }
        #pragma unroll
        for (int dd = 0; dd < HD; dd++) {
            int d = d0 + dd - 1;
            if ((unsigned)d >= (unsigned)ND) continue;
            float dep = __ldg(&dvals[b*ND + d]);
            float res[4];
            #pragma unroll
            for (int v = 0; v < 2; v++) {
                float px = rx[v]*dep + T[v][0];
                float py = ry[v]*dep + T[v][1];
                float pz = rz[v]*dep + T[v][2];
                if (fabsf(pz) < 1e-6f) pz = 1e-6f;
                res[v*2+0] = px / pz;
                res[v*2+1] = py / pz;
            }
            sPos[dd*PLANE + p] = make_float4(res[0], res[1], res[2], res[3]);
        }
    }
    __syncthreads();

    const int lw = tid & 31;
    const int lh = tid >> 5;
    float cost[TD];
    #pragma unroll
    for (int i = 0; i < TD; i++) cost[i] = 0.f;

    for (int cg = 0; cg < NC/4; cg++) {
        const float4* refBase = (const float4*)g_featT + ((size_t)(0*NB + b)*VB_STRIDE + (size_t)cg*CG_PLANE);
        const float4* v1Base  = (const float4*)g_featT + ((size_t)(1*NB + b)*VB_STRIDE + (size_t)cg*CG_PLANE);
        const float4* v2Base  = (const float4*)g_featT + ((size_t)(2*NB + b)*VB_STRIDE + (size_t)cg*CG_PLANE);

        // Phase A: variance for halo tile; ref load/squares hoisted out of depth loop
        for (int p = tid; p < PLANE; p += 256) {
            int hh = p / HWs;
            int ww = p - hh*HWs;
            int h = h0 + hh - 1, w = w0 + ww - 1;
            const bool valid = ((unsigned)h < (unsigned)NH && (unsigned)w < (unsigned)NW);
            float4 r4 = make_float4(0.f,0.f,0.f,0.f);
            if (valid) r4 = __ldg(refBase + (h*NW + w));
            const float rq0 = r4.x*r4.x, rq1 = r4.y*r4.y, rq2 = r4.z*r4.z, rq3 = r4.w*r4.w;
            #pragma unroll 2
            for (int dd = 0; dd < HD; dd++) {
                int d = d0 + dd - 1;
                float4 var = make_float4(0.f,0.f,0.f,0.f);
                if (valid && (unsigned)d < (unsigned)ND) {
                    float s0 = r4.x, s1 = r4.y, s2 = r4.z, s3 = r4.w;
                    float q0 = rq0, q1 = rq1, q2 = rq2, q3 = rq3;
                    float4 P = sPos[dd*PLANE + p];
                    bilin4(v1Base, P.x, P.y, s0, s1, s2, s3, q0, q1, q2, q3);
                    bilin4(v2Base, P.z, P.w, s0, s1, s2, s3, q0, q1, q2, q3);
                    const float inv3 = (1.f/3.f);
                    float m0 = s0*inv3, m1 = s1*inv3, m2 = s2*inv3, m3 = s3*inv3;
                    var = make_float4(q0*inv3 - m0*m0, q1*inv3 - m1*m1,
                                      q2*inv3 - m2*m2, q3*inv3 - m3*m3);
                }
                sVar[dd*PLANE + p] = var;
            }
        }
        __syncthreads();

        // Phase B: 3^3 conv accumulation, weights in registers
        const int c0 = cg*4;
        #pragma unroll
        for (int kh = 0; kh < 3; kh++) {
            #pragma unroll
            for (int kw = 0; kw < 3; kw++) {
                float wk[3][4];
                #pragma unroll
                for (int kd = 0; kd < 3; kd++) {
                    #pragma unroll
                    for (int cc = 0; cc < 4; cc++)
                        wk[kd][cc] = sW[((kd*3+kh)*3+kw)*NC + c0 + cc];
                }
                const float4* col = sVar + (lh+kh)*HWs + (lw+kw);
                #pragma unroll
                for (int dd = 0; dd < HD; dd++) {
                    float4 v = col[(size_t)dd*PLANE];
                    #pragma unroll
                    for (int kd = 0; kd < 3; kd++) {
                        int lo = dd - kd;
                        if (lo >= 0 && lo < TD) {
                            cost[lo] += v.x*wk[kd][0] + v.y*wk[kd][1]
                                      + v.z*wk[kd][2] + v.w*wk[kd][3];
                        }
                    }
                }
            }
        }
        __syncthreads();
    }

    const float bias = g_bias;
    #pragma unroll
    for (int lo = 0; lo < TD; lo++) {
        g_cost[((size_t)b*ND + d0+lo)*NHW + (h0+lh)*NW + (w0+lw)] = cost[lo] + bias;
    }
}

// ---------------- softmax over depth + expected depth + confidence ----------------
__global__ __launch_bounds__(256)
void softmax_kernel(const float* __restrict__ dvals, float* __restrict__ out) {
    int gid = blockIdx.x*blockDim.x + threadIdx.x;
    if (gid >= NB*NHW) return;
    int b = gid / NHW;
    int hw = gid - b*NHW;
    const float* cp = g_cost + (size_t)b*ND*NHW + hw;
    float c[ND];
    float mx = -3.4e38f;
    #pragma unroll
    for (int d = 0; d < ND; d++) {
        c[d] = cp[(size_t)d*NHW];
        mx = fmaxf(mx, c[d]);
    }
    float sum = 0.f;
    #pragma unroll
    for (int d = 0; d < ND; d++) {
        c[d] = __expf(c[d] - mx);
        sum += c[d];
    }
    float inv = 1.f/sum;
    float depth = 0.f, fidx = 0.f;
    #pragma unroll
    for (int d = 0; d < ND; d++) {
        depth += c[d]*__ldg(&dvals[b*ND + d]);
        fidx  += c[d]*(float)d;
    }
    depth *= inv;
    fidx  *= inv;
    int di = (int)fidx;
    di = min(max(di, 0), ND-1);
    float conf = 0.f;
    #pragma unroll
    for (int d = 0; d < ND; d++) {
        if (d >= di-1 && d <= di+2) conf += c[d];
    }
    conf *= inv;
    out[gid] = depth;
    out[NB*NHW + gid] = conf;
}

// ---------------- launch ----------------
extern "C" void kernel_launch(void* const* d_in, const int* in_sizes, int n_in,
                              void* d_out, int out_size) {
    const float* features = (const float*)d_in[0];   // (V,B,C,H,W)
    const float* proj     = (const float*)d_in[1];   // (B,V,4,4)
    const float* dvals    = (const float*)d_in[2];   // (B,D)
    int iw = 3;
    while (iw < n_in && in_sizes[iw] != 27*NC) iw++;
    const float* rw = (const float*)d_in[iw];
    const float* rb = (const float*)d_in[iw+1];

    cudaFuncSetAttribute(fused_cost_kernel,
                         cudaFuncAttributeMaxDynamicSharedMemorySize, SMEM_BYTES);

    prep_kernel<<<1, 256>>>(proj, rw, rb);
    transpose_kernel<<<dim3(NHW/32, NV*NB), dim3(32, 8)>>>(features);
    fused_cost_kernel<<<dim3(NW/TW, NH/TH, NB*(ND/TD)), 256, SMEM_BYTES>>>(dvals);
    softmax_kernel<<<(NB*NHW + 255)/256, 256>>>(dvals, (float*)d_out);
}